// round 8
// baseline (speedup 1.0000x reference)
#include <cuda_runtime.h>

// Problem constants
#define BATCH 2
#define DD 160
#define HH 160
#define WW 160
#define NTOT (BATCH * DD * HH * WW)   // 8192000
#define INV125 (1.0f / 125.0f)

// Tile config
#define TW 32               // tile width (voxels)
#define TPC 16              // pair-columns (TW/2), threadIdx.x
#define TH 16               // tile height, threadIdx.y
#define DCH 40              // depth chunk per block  -> 400 blocks
#define NCHUNK (DD / DCH)   // 4
#define NTHR 256
#define NBLK 400
#define SROWS (TH + 4)      // 20
#define SCOLS (TW + 4)      // 36
#define SCOLSP 38           // float2 stride: even -> every row 16B-aligned
#define SELEMS (SROWS * SCOLS)  // 720

// Depth ring in GLOBAL scratch (block-private slices, L2-resident).
// Per block: 5 rings x 256 threads x 40 B = 51.2 KB; total 20.5 MB.
__device__ float4 g_hista[NBLK][5][TH][TPC];   // {M0,M1,R0,R1}
__device__ float4 g_histb[NBLK][5][TH][TPC];   // {MM0,MM1,RR0,RR1}
__device__ float2 g_histc[NBLK][5][TH][TPC];   // {MR0,MR1}

__global__ void __launch_bounds__(NTHR, 3)
lncc_fused(const float* __restrict__ M,
           const float* __restrict__ R,
           float* __restrict__ out) {
    // Staging: interleaved (m, r) pairs.
    __shared__ float2 mr[SROWS][SCOLSP];                 // 6.08 KB
    // W-filtered fields, packed 2 per float4.
    __shared__ float4 tmpa[SROWS][TPC];                  // {M0,M1,R0,R1}
    __shared__ float4 tmpb[SROWS][TPC];                  // {MM0,MM1,RR0,RR1}
    __shared__ float2 tmpc[SROWS][TPC];                  // {MR0,MR1}

    const int tx  = threadIdx.x;          // 0..15 (pair col)
    const int ty  = threadIdx.y;          // 0..15 (row)
    const int tid = ty * TPC + tx;        // 0..255

    const int w0 = blockIdx.x * TW;
    const int h0 = blockIdx.y * TH;
    const int bz = blockIdx.z;            // b*NCHUNK + chunk
    const int b  = bz >> 2;               // NCHUNK == 4
    const int z0 = (bz & 3) * DCH;
    const int bid = (bz * gridDim.y + blockIdx.y) * gridDim.x + blockIdx.x;

    const size_t vol = (size_t)HH * WW;
    const float* Mb = M + (size_t)b * DD * vol;
    const float* Rb = R + (size_t)b * DD * vol;

    // Thread-private ring pointers (ring stride = TH*TPC float4/float2).
    float4* const pa = &g_hista[bid][0][ty][tx];
    float4* const pb = &g_histb[bid][0][ty][tx];
    float2* const pc = &g_histc[bid][0][ty][tx];

    // Zero own ring slots (thread-private; read later by same thread only).
#pragma unroll
    for (int j = 0; j < 5; j++) {
        pa[j * (TH * TPC)] = make_float4(0.f, 0.f, 0.f, 0.f);
        pb[j * (TH * TPC)] = make_float4(0.f, 0.f, 0.f, 0.f);
        pc[j * (TH * TPC)] = make_float2(0.f, 0.f);
    }

    // ---- Loop-invariant staging metadata ----
    int  goff[3], soff[3];
    bool inb[3];
#pragma unroll
    for (int k = 0; k < 3; k++) {
        const int i = tid + k * NTHR;
        const bool vld = (i < SELEMS);
        int row = 0, col = 0, h = 0, w = 0;
        if (vld) {
            row = i / SCOLS;
            col = i - row * SCOLS;
            h = h0 - 2 + row;
            w = w0 - 2 + col;
        }
        const bool ok = vld & ((unsigned)h < HH) & ((unsigned)w < WW);
        inb[k]  = ok;
        goff[k] = ok ? (h * WW + w) : 0;
        soff[k] = row * SCOLSP + col;
    }

    float2* const mrf = &mr[0][0];

    // Pre-zero the whole staging buffer once: spatially-OOB slots stay zero
    // forever; in-bounds slots are overwritten every plane.
    for (int i = tid; i < SROWS * SCOLSP; i += NTHR)
        mrf[i] = make_float2(0.f, 0.f);

    // Running D-window sums, in registers.
    float4 runs_ab = make_float4(0.f, 0.f, 0.f, 0.f);
    float4 runs_cd = make_float4(0.f, 0.f, 0.f, 0.f);
    float2 runs_e  = make_float2(0.f, 0.f);

    float acc = 0.f;
    int rp = 0;

    // ---- Prefetch first plane (z0-2) ----
    float pm[3], pr[3];
    {
        const int z = z0 - 2;
        const bool okz = (z >= 0);
#pragma unroll
        for (int k = 0; k < 3; k++) {
            float mv = 0.f, rv = 0.f;
            if (okz & inb[k]) {
                const size_t g = (size_t)z * vol + goff[k];
                mv = Mb[g]; rv = Rb[g];
            }
            pm[k] = mv; pr[k] = rv;
        }
    }

    for (int s = 0; s < DCH + 4; s++) {
        // ---- Commit prefetched plane to staging (in-bounds slots only) ----
#pragma unroll
        for (int k = 0; k < 3; k++)
            if (inb[k]) mrf[soff[k]] = make_float2(pm[k], pr[k]);
        __syncthreads();

        // ---- Prefetch next input plane (DRAM latency hidden by stages) ----
        {
            const int z = z0 - 1 + s;
            const bool okz = ((unsigned)z < DD);
#pragma unroll
            for (int k = 0; k < 3; k++) {
                float mv = 0.f, rv = 0.f;
                if (okz & inb[k]) {
                    const size_t g = (size_t)z * vol + goff[k];
                    mv = Mb[g]; rv = Rb[g];
                }
                pm[k] = mv; pr[k] = rv;
            }
        }

        // ---- Hoist ring-old loads (L2 latency hidden by stage 2) ----
        const float4 oa = pa[rp * (TH * TPC)];
        const float4 ob = pb[rp * (TH * TPC)];
        const float2 oc = pc[rp * (TH * TPC)];

        // ---- Stage 2: W-filter 5 products (320 positions, wide LDS) ----
        auto do_pos = [&](int i) {
            const int row = i >> 4;
            const int pc4 = i & 15;
            const int xb  = 2 * pc4;
            const float4 q0 = *(const float4*)&mr[row][xb];      // m0 r0 m1 r1
            const float4 q1 = *(const float4*)&mr[row][xb + 2];  // m2 r2 m3 r3
            const float4 q2 = *(const float4*)&mr[row][xb + 4];  // m4 r4 m5 r5
            const float m0 = q0.x, r0 = q0.y, m1 = q0.z, r1 = q0.w;
            const float m2 = q1.x, r2 = q1.y, m3 = q1.z, r3 = q1.w;
            const float m4 = q2.x, r4 = q2.y, m5 = q2.z, r5 = q2.w;

            const float tM  = m1 + m2 + m3 + m4;
            const float tR  = r1 + r2 + r3 + r4;
            const float tMM = fmaf(m1, m1, fmaf(m2, m2, fmaf(m3, m3, m4 * m4)));
            const float tRR = fmaf(r1, r1, fmaf(r2, r2, fmaf(r3, r3, r4 * r4)));
            const float tMR = fmaf(m1, r1, fmaf(m2, r2, fmaf(m3, r3, m4 * r4)));

            tmpa[row][pc4] = make_float4(tM + m0, tM + m5, tR + r0, tR + r5);
            tmpb[row][pc4] = make_float4(fmaf(m0, m0, tMM), fmaf(m5, m5, tMM),
                                         fmaf(r0, r0, tRR), fmaf(r5, r5, tRR));
            tmpc[row][pc4] = make_float2(fmaf(m0, r0, tMR), fmaf(m5, r5, tMR));
        };
        do_pos(tid);
        if (tid < SROWS * TPC - NTHR) do_pos(tid + NTHR);
        __syncthreads();

        // ---- Stage 3: H-filter (wide taps) + global-ring D update ----
        {
            float4 s_ab = make_float4(0.f, 0.f, 0.f, 0.f);
            float4 s_cd = make_float4(0.f, 0.f, 0.f, 0.f);
            float2 s_e  = make_float2(0.f, 0.f);
#pragma unroll
            for (int j = 0; j < 5; j++) {
                const float4 a = tmpa[ty + j][tx];
                const float4 c = tmpb[ty + j][tx];
                const float2 e = tmpc[ty + j][tx];
                s_ab.x += a.x; s_ab.y += a.y; s_ab.z += a.z; s_ab.w += a.w;
                s_cd.x += c.x; s_cd.y += c.y; s_cd.z += c.z; s_cd.w += c.w;
                s_e.x  += e.x; s_e.y  += e.y;
            }
            runs_ab.x += s_ab.x - oa.x; runs_ab.y += s_ab.y - oa.y;
            runs_ab.z += s_ab.z - oa.z; runs_ab.w += s_ab.w - oa.w;
            runs_cd.x += s_cd.x - ob.x; runs_cd.y += s_cd.y - ob.y;
            runs_cd.z += s_cd.z - ob.z; runs_cd.w += s_cd.w - ob.w;
            runs_e.x  += s_e.x  - oc.x; runs_e.y  += s_e.y  - oc.y;
            pa[rp * (TH * TPC)] = s_ab;
            pb[rp * (TH * TPC)] = s_cd;
            pc[rp * (TH * TPC)] = s_e;
        }

        rp = (rp == 4) ? 0 : rp + 1;

        // ---- Stage 4: emit output plane zout = zin - 2 ----
        if (s >= 4) {
#pragma unroll
            for (int c = 0; c < 2; c++) {
                const float Mm  = (c ? runs_ab.y : runs_ab.x) * INV125;
                const float Rm  = (c ? runs_ab.w : runs_ab.z) * INV125;
                const float MMm = (c ? runs_cd.y : runs_cd.x) * INV125;
                const float RRm = (c ? runs_cd.w : runs_cd.z) * INV125;
                const float MRm = (c ? runs_e.y  : runs_e.x ) * INV125;

                const float a   = fmaf(-Mm, Mm, MMm) + 1e-5f;
                const float bb  = fmaf(-Rm, Rm, RRm) + 1e-5f;
                const float num = fmaf(-Mm, Rm, MRm);
                const float ab  = a * bb;
                const float den = ab * rsqrtf(ab) + 1e-5f;  // sqrt(a)*sqrt(b)+eps
                acc += __fdividef(num, den);
            }
        }
    }

    // ---- Block reduction (256 threads) + atomic ----
    __shared__ float warp_sums[NTHR / 32];
    float v = acc;
#pragma unroll
    for (int off = 16; off > 0; off >>= 1)
        v += __shfl_xor_sync(0xFFFFFFFFu, v, off);
    if ((tid & 31) == 0) warp_sums[tid >> 5] = v;
    __syncthreads();
    if (tid < 32) {
        float sWS = (tid < NTHR / 32) ? warp_sums[tid] : 0.f;
#pragma unroll
        for (int off = 4; off > 0; off >>= 1)
            sWS += __shfl_xor_sync(0xFFFFFFFFu, sWS, off);
        if (tid == 0)
            atomicAdd(out, -sWS * (1.0f / (float)NTOT));
    }
}

__global__ void lncc_zero_out(float* out) { out[0] = 0.f; }

// ---------------------------------------------------------------------------
extern "C" void kernel_launch(void* const* d_in, const int* in_sizes, int n_in,
                              void* d_out, int out_size) {
    const float* M = (const float*)d_in[0];
    const float* R = (const float*)d_in[1];
    // d_in[2] is the box kernel (ones/125) — folded into INV125.
    float* out = (float*)d_out;

    lncc_zero_out<<<1, 1>>>(out);

    dim3 blk(TPC, TH, 1);                                   // (16,16) = 256
    dim3 grd(WW / TW, HH / TH, BATCH * NCHUNK);             // (5,10,8) = 400
    lncc_fused<<<grd, blk>>>(M, R, out);
}

// round 9
// speedup vs baseline: 1.2683x; 1.2683x over previous
#include <cuda_runtime.h>

// Problem constants
#define BATCH 2
#define DD 160
#define HH 160
#define WW 160
#define NTOT (BATCH * DD * HH * WW)   // 8192000
#define INV125 (1.0f / 125.0f)

// Tile config
#define TW 32               // tile width (voxels)
#define TPC 16              // pair-columns (TW/2), threadIdx.x
#define TH 16               // tile height, threadIdx.y
#define DCH 40              // depth chunk per block  -> 400 blocks
#define NCHUNK (DD / DCH)   // 4
#define NTHR 256
#define SROWS (TH + 4)      // 20
#define SCOLS (TW + 4)      // 36
#define SCOLSP 38           // float2 stride: even -> every row 16B-aligned
#define SELEMS (SROWS * SCOLS)  // 720

__global__ void __launch_bounds__(NTHR, 3)
lncc_fused(const float* __restrict__ M,
           const float* __restrict__ R,
           float* __restrict__ out) {
    // Double-buffered staging: interleaved (m, r) pairs.
    __shared__ float2 mr2[2][SROWS][SCOLSP];             // 12.16 KB
    // Depth ring (5 planes of HW-filtered sums), packed.
    __shared__ float4 hista[5][TH][TPC];                 // {M0,M1,R0,R1}
    __shared__ float4 histb[5][TH][TPC];                 // {MM0,MM1,RR0,RR1}
    __shared__ float2 histc[5][TH][TPC];                 // {MR0,MR1}

    const int tx  = threadIdx.x;          // 0..15 (pair col)
    const int ty  = threadIdx.y;          // 0..15 (row)
    const int tid = ty * TPC + tx;        // 0..255

    const int w0 = blockIdx.x * TW;
    const int h0 = blockIdx.y * TH;
    const int bz = blockIdx.z;            // b*NCHUNK + chunk
    const int b  = bz >> 2;               // NCHUNK == 4
    const int z0 = (bz & 3) * DCH;

    const size_t vol = (size_t)HH * WW;
    const float* Mb = M + (size_t)b * DD * vol;
    const float* Rb = R + (size_t)b * DD * vol;

    // ---- Loop-invariant staging metadata ----
    int  goff[3], soff[3];
    bool inb[3];
#pragma unroll
    for (int k = 0; k < 3; k++) {
        const int i = tid + k * NTHR;
        const bool vld = (i < SELEMS);
        int row = 0, col = 0, h = 0, w = 0;
        if (vld) {
            row = i / SCOLS;
            col = i - row * SCOLS;
            h = h0 - 2 + row;
            w = w0 - 2 + col;
        }
        const bool ok = vld & ((unsigned)h < HH) & ((unsigned)w < WW);
        inb[k]  = ok;
        goff[k] = ok ? (h * WW + w) : 0;
        soff[k] = row * SCOLSP + col;
    }

    // Pre-zero both staging buffers (OOB slots stay zero forever).
    {
        float2* const m0f = &mr2[0][0][0];
        for (int i = tid; i < 2 * SROWS * SCOLSP; i += NTHR)
            m0f[i] = make_float2(0.f, 0.f);
    }

    // Zero own ring slots (thread-private; no barrier needed).
#pragma unroll
    for (int j = 0; j < 5; j++) {
        hista[j][ty][tx] = make_float4(0.f, 0.f, 0.f, 0.f);
        histb[j][ty][tx] = make_float4(0.f, 0.f, 0.f, 0.f);
        histc[j][ty][tx] = make_float2(0.f, 0.f);
    }

    // Running D-window sums, in registers.
    float4 runs_ab = make_float4(0.f, 0.f, 0.f, 0.f);   // {M0,M1,R0,R1}
    float4 runs_cd = make_float4(0.f, 0.f, 0.f, 0.f);   // {MM0,MM1,RR0,RR1}
    float2 runs_e  = make_float2(0.f, 0.f);             // {MR0,MR1}

    float acc = 0.f;
    int rp = 0;

    // ---- Prefetch first plane (z0-2) ----
    float pm[3], pr[3];
    {
        const int z = z0 - 2;
        const bool okz = (z >= 0);
#pragma unroll
        for (int k = 0; k < 3; k++) {
            float mv = 0.f, rv = 0.f;
            if (okz & inb[k]) {
                const size_t g = (size_t)z * vol + goff[k];
                mv = Mb[g]; rv = Rb[g];
            }
            pm[k] = mv; pr[k] = rv;
        }
    }

    for (int s = 0; s < DCH + 4; s++) {
        const int bi = s & 1;
        float2* const buf = &mr2[bi][0][0];

        // ---- Commit prefetched plane to staging (in-bounds slots only) ----
        // Safe vs readers of this buffer (iteration s-2): their reads precede
        // their commit at s-1 which precedes BAR(s-1), and this commit follows
        // our read at s-1 which follows BAR(s-1).
#pragma unroll
        for (int k = 0; k < 3; k++)
            if (inb[k]) buf[soff[k]] = make_float2(pm[k], pr[k]);
        __syncthreads();

        // ---- Prefetch next input plane (DRAM latency hidden by compute) ----
        {
            const int z = z0 - 1 + s;
            const bool okz = ((unsigned)z < DD) & (s < DCH + 3);
#pragma unroll
            for (int k = 0; k < 3; k++) {
                float mv = 0.f, rv = 0.f;
                if (okz & inb[k]) {
                    const size_t g = (size_t)z * vol + goff[k];
                    mv = Mb[g]; rv = Rb[g];
                }
                pm[k] = mv; pr[k] = rv;
            }
        }

        // ---- Hoist ring-old loads ----
        const float4 oa = hista[rp][ty][tx];
        const float4 ob = histb[rp][ty][tx];
        const float2 oc = histc[rp][ty][tx];

        // ---- Direct H x W filter from staging (5 rows x 6 cols) ----
        float4 s_ab = make_float4(0.f, 0.f, 0.f, 0.f);
        float4 s_cd = make_float4(0.f, 0.f, 0.f, 0.f);
        float2 s_e  = make_float2(0.f, 0.f);
        const int xb = 2 * tx;   // staging col of leftmost halo pair
#pragma unroll
        for (int j = 0; j < 5; j++) {
            const float2* rowp = &mr2[bi][ty + j][xb];
            const float4 q0 = *(const float4*)(rowp);      // m0 r0 m1 r1
            const float4 q1 = *(const float4*)(rowp + 2);  // m2 r2 m3 r3
            const float4 q2 = *(const float4*)(rowp + 4);  // m4 r4 m5 r5
            const float m0 = q0.x, r0 = q0.y, m1 = q0.z, r1 = q0.w;
            const float m2 = q1.x, r2 = q1.y, m3 = q1.z, r3 = q1.w;
            const float m4 = q2.x, r4 = q2.y, m5 = q2.z, r5 = q2.w;

            // shared middle partials (cols 1..4)
            const float tM  = m1 + m2 + m3 + m4;
            const float tR  = r1 + r2 + r3 + r4;
            const float tMM = fmaf(m1, m1, fmaf(m2, m2, fmaf(m3, m3, m4 * m4)));
            const float tRR = fmaf(r1, r1, fmaf(r2, r2, fmaf(r3, r3, r4 * r4)));
            const float tMR = fmaf(m1, r1, fmaf(m2, r2, fmaf(m3, r3, m4 * r4)));

            s_ab.x += tM + m0;  s_ab.y += tM + m5;
            s_ab.z += tR + r0;  s_ab.w += tR + r5;
            s_cd.x += fmaf(m0, m0, tMM);  s_cd.y += fmaf(m5, m5, tMM);
            s_cd.z += fmaf(r0, r0, tRR);  s_cd.w += fmaf(r5, r5, tRR);
            s_e.x  += fmaf(m0, r0, tMR);  s_e.y  += fmaf(m5, r5, tMR);
        }

        // ---- Ring D update (incremental window) ----
        runs_ab.x += s_ab.x - oa.x; runs_ab.y += s_ab.y - oa.y;
        runs_ab.z += s_ab.z - oa.z; runs_ab.w += s_ab.w - oa.w;
        runs_cd.x += s_cd.x - ob.x; runs_cd.y += s_cd.y - ob.y;
        runs_cd.z += s_cd.z - ob.z; runs_cd.w += s_cd.w - ob.w;
        runs_e.x  += s_e.x  - oc.x; runs_e.y  += s_e.y  - oc.y;
        hista[rp][ty][tx] = s_ab;
        histb[rp][ty][tx] = s_cd;
        histc[rp][ty][tx] = s_e;

        rp = (rp == 4) ? 0 : rp + 1;

        // ---- Emit output plane zout = zin - 2 ----
        if (s >= 4) {
#pragma unroll
            for (int c = 0; c < 2; c++) {
                const float Mm  = (c ? runs_ab.y : runs_ab.x) * INV125;
                const float Rm  = (c ? runs_ab.w : runs_ab.z) * INV125;
                const float MMm = (c ? runs_cd.y : runs_cd.x) * INV125;
                const float RRm = (c ? runs_cd.w : runs_cd.z) * INV125;
                const float MRm = (c ? runs_e.y  : runs_e.x ) * INV125;

                const float a   = fmaf(-Mm, Mm, MMm) + 1e-5f;
                const float bb  = fmaf(-Rm, Rm, RRm) + 1e-5f;
                const float num = fmaf(-Mm, Rm, MRm);
                const float ab  = a * bb;
                const float den = ab * rsqrtf(ab) + 1e-5f;  // sqrt(a)*sqrt(b)+eps
                acc += __fdividef(num, den);
            }
        }
    }

    // ---- Block reduction (256 threads) + atomic ----
    __shared__ float warp_sums[NTHR / 32];
    float v = acc;
#pragma unroll
    for (int off = 16; off > 0; off >>= 1)
        v += __shfl_xor_sync(0xFFFFFFFFu, v, off);
    if ((tid & 31) == 0) warp_sums[tid >> 5] = v;
    __syncthreads();
    if (tid < 32) {
        float sWS = (tid < NTHR / 32) ? warp_sums[tid] : 0.f;
#pragma unroll
        for (int off = 4; off > 0; off >>= 1)
            sWS += __shfl_xor_sync(0xFFFFFFFFu, sWS, off);
        if (tid == 0)
            atomicAdd(out, -sWS * (1.0f / (float)NTOT));
    }
}

__global__ void lncc_zero_out(float* out) { out[0] = 0.f; }

// ---------------------------------------------------------------------------
extern "C" void kernel_launch(void* const* d_in, const int* in_sizes, int n_in,
                              void* d_out, int out_size) {
    const float* M = (const float*)d_in[0];
    const float* R = (const float*)d_in[1];
    // d_in[2] is the box kernel (ones/125) — folded into INV125.
    float* out = (float*)d_out;

    lncc_zero_out<<<1, 1>>>(out);

    dim3 blk(TPC, TH, 1);                                   // (16,16) = 256
    dim3 grd(WW / TW, HH / TH, BATCH * NCHUNK);             // (5,10,8) = 400
    lncc_fused<<<grd, blk>>>(M, R, out);
}

// round 10
// speedup vs baseline: 1.4367x; 1.1327x over previous
#include <cuda_runtime.h>

// Problem constants
#define BATCH 2
#define DD 160
#define HH 160
#define WW 160
#define NTOT (BATCH * DD * HH * WW)   // 8192000
#define INV125 (1.0f / 125.0f)

// Tile config: 32(W) x 16(H) tile, 4 voxels/thread (2 rows x 2 cols)
#define TW 32               // tile width (voxels)
#define TPC 16              // pair-columns (TW/2), threadIdx.x
#define TH 16               // tile height (voxels)
#define TRH 8               // thread rows (TH/2), threadIdx.y
#define DCH 40              // depth chunk per block  -> 400 blocks
#define NCHUNK (DD / DCH)   // 4
#define NTHR 128
#define KSLOTS 6            // ceil(720/128)
#define SROWS (TH + 4)      // 20
#define SCOLS (TW + 4)      // 36
#define SCOLSP 38           // float2 stride: even -> every row 16B-aligned
#define SELEMS (SROWS * SCOLS)  // 720

__global__ void __launch_bounds__(NTHR, 3)
lncc_fused(const float* __restrict__ M,
           const float* __restrict__ R,
           float* __restrict__ out) {
    // Double-buffered staging: interleaved (m, r) pairs.
    __shared__ float2 mr2[2][SROWS][SCOLSP];             // 12.16 KB
    // Depth ring (5 planes of HW-filtered sums), packed; indexed by voxel row.
    __shared__ float4 hista[5][TH][TPC];                 // {M0,M1,R0,R1}
    __shared__ float4 histb[5][TH][TPC];                 // {MM0,MM1,RR0,RR1}
    __shared__ float2 histc[5][TH][TPC];                 // {MR0,MR1}

    const int tx  = threadIdx.x;          // 0..15 (pair col)
    const int ty  = threadIdx.y;          // 0..7  (row pair)
    const int tid = ty * TPC + tx;        // 0..127
    const int y0  = 2 * ty;               // first output row

    const int w0 = blockIdx.x * TW;
    const int h0 = blockIdx.y * TH;
    const int bz = blockIdx.z;            // b*NCHUNK + chunk
    const int b  = bz >> 2;               // NCHUNK == 4
    const int z0 = (bz & 3) * DCH;

    const size_t vol = (size_t)HH * WW;
    const float* Mb = M + (size_t)b * DD * vol;
    const float* Rb = R + (size_t)b * DD * vol;

    // ---- Loop-invariant staging metadata ----
    int  goff[KSLOTS], soff[KSLOTS];
    bool inb[KSLOTS];
#pragma unroll
    for (int k = 0; k < KSLOTS; k++) {
        const int i = tid + k * NTHR;
        const bool vld = (i < SELEMS);
        int row = 0, col = 0, h = 0, w = 0;
        if (vld) {
            row = i / SCOLS;
            col = i - row * SCOLS;
            h = h0 - 2 + row;
            w = w0 - 2 + col;
        }
        const bool ok = vld & ((unsigned)h < HH) & ((unsigned)w < WW);
        inb[k]  = ok;
        goff[k] = ok ? (h * WW + w) : 0;
        soff[k] = row * SCOLSP + col;
    }

    // Pre-zero both staging buffers (OOB slots stay zero forever).
    {
        float2* const m0f = &mr2[0][0][0];
        for (int i = tid; i < 2 * SROWS * SCOLSP; i += NTHR)
            m0f[i] = make_float2(0.f, 0.f);
    }

    // Zero own ring slots (thread-private; no barrier needed).
#pragma unroll
    for (int j = 0; j < 5; j++) {
#pragma unroll
        for (int g = 0; g < 2; g++) {
            hista[j][y0 + g][tx] = make_float4(0.f, 0.f, 0.f, 0.f);
            histb[j][y0 + g][tx] = make_float4(0.f, 0.f, 0.f, 0.f);
            histc[j][y0 + g][tx] = make_float2(0.f, 0.f);
        }
    }

    // Running D-window sums (per row group), in registers.
    float4 runs_ab[2], runs_cd[2];
    float2 runs_e[2];
#pragma unroll
    for (int g = 0; g < 2; g++) {
        runs_ab[g] = make_float4(0.f, 0.f, 0.f, 0.f);
        runs_cd[g] = make_float4(0.f, 0.f, 0.f, 0.f);
        runs_e[g]  = make_float2(0.f, 0.f);
    }

    float acc = 0.f;
    int rp = 0;

    // ---- Prefetch first plane (z0-2) ----
    float pm[KSLOTS], pr[KSLOTS];
    {
        const int z = z0 - 2;
        const bool okz = (z >= 0);
#pragma unroll
        for (int k = 0; k < KSLOTS; k++) {
            float mv = 0.f, rv = 0.f;
            if (okz & inb[k]) {
                const size_t g = (size_t)z * vol + goff[k];
                mv = Mb[g]; rv = Rb[g];
            }
            pm[k] = mv; pr[k] = rv;
        }
    }

    for (int s = 0; s < DCH + 4; s++) {
        const int bi = s & 1;
        float2* const buf = &mr2[bi][0][0];

        // ---- Commit prefetched plane to staging (in-bounds slots only) ----
#pragma unroll
        for (int k = 0; k < KSLOTS; k++)
            if (inb[k]) buf[soff[k]] = make_float2(pm[k], pr[k]);
        __syncthreads();

        // ---- Prefetch next input plane (DRAM latency hidden by compute) ----
        {
            const int z = z0 - 1 + s;
            const bool okz = ((unsigned)z < DD) & (s < DCH + 3);
#pragma unroll
            for (int k = 0; k < KSLOTS; k++) {
                float mv = 0.f, rv = 0.f;
                if (okz & inb[k]) {
                    const size_t g = (size_t)z * vol + goff[k];
                    mv = Mb[g]; rv = Rb[g];
                }
                pm[k] = mv; pr[k] = rv;
            }
        }

        // ---- Direct H x W filter: 6 staging rows feed 2 output rows ----
        float4 sab0 = make_float4(0.f, 0.f, 0.f, 0.f);
        float4 scd0 = make_float4(0.f, 0.f, 0.f, 0.f);
        float2 se0  = make_float2(0.f, 0.f);
        float4 sab1 = sab0;
        float4 scd1 = scd0;
        float2 se1  = se0;
        const int xb = 2 * tx;   // staging col of leftmost halo pair
#pragma unroll
        for (int j = 0; j < 6; j++) {
            const float2* rowp = &mr2[bi][y0 + j][xb];
            const float4 q0 = *(const float4*)(rowp);      // m0 r0 m1 r1
            const float4 q1 = *(const float4*)(rowp + 2);  // m2 r2 m3 r3
            const float4 q2 = *(const float4*)(rowp + 4);  // m4 r4 m5 r5
            const float m0 = q0.x, r0 = q0.y, m1 = q0.z, r1 = q0.w;
            const float m2 = q1.x, r2 = q1.y, m3 = q1.z, r3 = q1.w;
            const float m4 = q2.x, r4 = q2.y, m5 = q2.z, r5 = q2.w;

            // shared middle partials (cols 1..4)
            const float tM  = m1 + m2 + m3 + m4;
            const float tR  = r1 + r2 + r3 + r4;
            const float tMM = fmaf(m1, m1, fmaf(m2, m2, fmaf(m3, m3, m4 * m4)));
            const float tRR = fmaf(r1, r1, fmaf(r2, r2, fmaf(r3, r3, r4 * r4)));
            const float tMR = fmaf(m1, r1, fmaf(m2, r2, fmaf(m3, r3, m4 * r4)));

            const float aM0 = tM + m0,           aM1 = tM + m5;
            const float aR0 = tR + r0,           aR1 = tR + r5;
            const float aMM0 = fmaf(m0, m0, tMM), aMM1 = fmaf(m5, m5, tMM);
            const float aRR0 = fmaf(r0, r0, tRR), aRR1 = fmaf(r5, r5, tRR);
            const float aMR0 = fmaf(m0, r0, tMR), aMR1 = fmaf(m5, r5, tMR);

            if (j < 5) {   // compile-time guards: window rows 0..4
                sab0.x += aM0;  sab0.y += aM1;  sab0.z += aR0;  sab0.w += aR1;
                scd0.x += aMM0; scd0.y += aMM1; scd0.z += aRR0; scd0.w += aRR1;
                se0.x  += aMR0; se0.y  += aMR1;
            }
            if (j > 0) {   // window rows 1..5
                sab1.x += aM0;  sab1.y += aM1;  sab1.z += aR0;  sab1.w += aR1;
                scd1.x += aMM0; scd1.y += aMM1; scd1.z += aRR0; scd1.w += aRR1;
                se1.x  += aMR0; se1.y  += aMR1;
            }
        }

        // ---- Ring D update (incremental window), both row groups ----
#pragma unroll
        for (int g = 0; g < 2; g++) {
            const float4 s_ab = g ? sab1 : sab0;
            const float4 s_cd = g ? scd1 : scd0;
            const float2 s_e  = g ? se1  : se0;
            const float4 oa = hista[rp][y0 + g][tx];
            const float4 ob = histb[rp][y0 + g][tx];
            const float2 oc = histc[rp][y0 + g][tx];
            runs_ab[g].x += s_ab.x - oa.x; runs_ab[g].y += s_ab.y - oa.y;
            runs_ab[g].z += s_ab.z - oa.z; runs_ab[g].w += s_ab.w - oa.w;
            runs_cd[g].x += s_cd.x - ob.x; runs_cd[g].y += s_cd.y - ob.y;
            runs_cd[g].z += s_cd.z - ob.z; runs_cd[g].w += s_cd.w - ob.w;
            runs_e[g].x  += s_e.x  - oc.x; runs_e[g].y  += s_e.y  - oc.y;
            hista[rp][y0 + g][tx] = s_ab;
            histb[rp][y0 + g][tx] = s_cd;
            histc[rp][y0 + g][tx] = s_e;
        }

        rp = (rp == 4) ? 0 : rp + 1;

        // ---- Emit output plane zout = zin - 2 (4 voxels) ----
        if (s >= 4) {
#pragma unroll
            for (int g = 0; g < 2; g++) {
#pragma unroll
                for (int c = 0; c < 2; c++) {
                    const float Mm  = (c ? runs_ab[g].y : runs_ab[g].x) * INV125;
                    const float Rm  = (c ? runs_ab[g].w : runs_ab[g].z) * INV125;
                    const float MMm = (c ? runs_cd[g].y : runs_cd[g].x) * INV125;
                    const float RRm = (c ? runs_cd[g].w : runs_cd[g].z) * INV125;
                    const float MRm = (c ? runs_e[g].y  : runs_e[g].x ) * INV125;

                    const float a   = fmaf(-Mm, Mm, MMm) + 1e-5f;
                    const float bb  = fmaf(-Rm, Rm, RRm) + 1e-5f;
                    const float num = fmaf(-Mm, Rm, MRm);
                    const float ab  = a * bb;
                    const float den = ab * rsqrtf(ab) + 1e-5f; // sqrt(a)*sqrt(b)+eps
                    acc += __fdividef(num, den);
                }
            }
        }
    }

    // ---- Block reduction (128 threads) + atomic ----
    __shared__ float warp_sums[NTHR / 32];
    float v = acc;
#pragma unroll
    for (int off = 16; off > 0; off >>= 1)
        v += __shfl_xor_sync(0xFFFFFFFFu, v, off);
    if ((tid & 31) == 0) warp_sums[tid >> 5] = v;
    __syncthreads();
    if (tid < 32) {
        float sWS = (tid < NTHR / 32) ? warp_sums[tid] : 0.f;
#pragma unroll
        for (int off = 2; off > 0; off >>= 1)
            sWS += __shfl_xor_sync(0xFFFFFFFFu, sWS, off);
        if (tid == 0)
            atomicAdd(out, -sWS * (1.0f / (float)NTOT));
    }
}

__global__ void lncc_zero_out(float* out) { out[0] = 0.f; }

// ---------------------------------------------------------------------------
extern "C" void kernel_launch(void* const* d_in, const int* in_sizes, int n_in,
                              void* d_out, int out_size) {
    const float* M = (const float*)d_in[0];
    const float* R = (const float*)d_in[1];
    // d_in[2] is the box kernel (ones/125) — folded into INV125.
    float* out = (float*)d_out;

    lncc_zero_out<<<1, 1>>>(out);

    dim3 blk(TPC, TRH, 1);                                  // (16,8) = 128
    dim3 grd(WW / TW, HH / TH, BATCH * NCHUNK);             // (5,10,8) = 400
    lncc_fused<<<grd, blk>>>(M, R, out);
}